// round 3
// baseline (speedup 1.0000x reference)
#include <cuda_runtime.h>

// SpectralAttention: B=1024, S=3, A=256, D=256
// HBM-bound streaming reduction (1.07 GB reads; 91% of spec reached in R2).
// R3: persistent grid-stride kernel (no CTA churn / wave transitions) with a
// 2-stage software pipeline: next iteration's 8x LDG.128 issue before the
// current iteration's FMAs/reduction, keeping DRAM queues continuously full.

#define BB 1024
#define SS 3
#define AA 256
#define DD 256
#define TOT (BB * AA)          // 262144 (b,a) pairs
#define NSM 152                 // GB300
#define CTAS (NSM * 4)          // 608 persistent CTAs
#define WARPS_PER_CTA 8

__device__ __forceinline__ void load_rows(int idx, int lane,
                                          const float* __restrict__ input,
                                          const float* __restrict__ scattered,
                                          float4 v[8])
{
    const int b = idx >> 8;
    const int a = idx & 255;
    const float4* __restrict__ xr =
        reinterpret_cast<const float4*>(input + (((size_t)b * AA + a) * DD));
    const float4* __restrict__ y0r = reinterpret_cast<const float4*>(
        scattered + ((((size_t)b * SS + 0) * AA + a) * (size_t)DD));
    const float4* __restrict__ y1r = reinterpret_cast<const float4*>(
        scattered + ((((size_t)b * SS + 1) * AA + a) * (size_t)DD));
    const float4* __restrict__ y2r = reinterpret_cast<const float4*>(
        scattered + ((((size_t)b * SS + 2) * AA + a) * (size_t)DD));
    v[0] = __ldcs(&xr[lane]);
    v[1] = __ldcs(&xr[lane + 32]);
    v[2] = __ldcs(&y0r[lane]);
    v[3] = __ldcs(&y0r[lane + 32]);
    v[4] = __ldcs(&y1r[lane]);
    v[5] = __ldcs(&y1r[lane + 32]);
    v[6] = __ldcs(&y2r[lane]);
    v[7] = __ldcs(&y2r[lane + 32]);
}

__global__ __launch_bounds__(256, 2)
void spectral_attention_kernel(const float* __restrict__ input,
                               const float* __restrict__ scattered,
                               const float* __restrict__ weight,
                               const float* __restrict__ prelu,
                               float* __restrict__ out)
{
    const int lane = threadIdx.x & 31;
    const int gwarp = (blockIdx.x * blockDim.x + threadIdx.x) >> 5;
    const int stride = CTAS * WARPS_PER_CTA;   // 4864 warps total

    // Weights: 512 floats = 128 float4, L1-resident after first touch.
    const float4* __restrict__ wv = reinterpret_cast<const float4*>(weight);
    const float4 w1a = __ldg(&wv[lane]);
    const float4 w1b = __ldg(&wv[lane + 32]);
    const float4 w2a = __ldg(&wv[64 + lane]);
    const float4 w2b = __ldg(&wv[64 + lane + 32]);
    const float alpha = __ldg(prelu);

    int idx = gwarp;
    float4 cur[8];
    bool valid = (idx < TOT);
    if (valid) load_rows(idx, lane, input, scattered, cur);

    while (valid) {
        // ---- Stage: issue next iteration's loads first (latency hiding) ----
        const int nidx = idx + stride;
        const bool nvalid = (nidx < TOT);
        float4 nxt[8];
        if (nvalid) load_rows(nidx, lane, input, scattered, nxt);

        // ---- Consume current iteration ----
        float p_in = cur[0].x*w1a.x + cur[0].y*w1a.y + cur[0].z*w1a.z + cur[0].w*w1a.w
                   + cur[1].x*w1b.x + cur[1].y*w1b.y + cur[1].z*w1b.z + cur[1].w*w1b.w;
        float p0   = cur[2].x*w2a.x + cur[2].y*w2a.y + cur[2].z*w2a.z + cur[2].w*w2a.w
                   + cur[3].x*w2b.x + cur[3].y*w2b.y + cur[3].z*w2b.z + cur[3].w*w2b.w;
        float p1   = cur[4].x*w2a.x + cur[4].y*w2a.y + cur[4].z*w2a.z + cur[4].w*w2a.w
                   + cur[5].x*w2b.x + cur[5].y*w2b.y + cur[5].z*w2b.z + cur[5].w*w2b.w;
        float p2   = cur[6].x*w2a.x + cur[6].y*w2a.y + cur[6].z*w2a.z + cur[6].w*w2a.w
                   + cur[7].x*w2b.x + cur[7].y*w2b.y + cur[7].z*w2b.z + cur[7].w*w2b.w;

#pragma unroll
        for (int off = 16; off > 0; off >>= 1) {
            p_in += __shfl_xor_sync(0xffffffffu, p_in, off);
            p0   += __shfl_xor_sync(0xffffffffu, p0, off);
            p1   += __shfl_xor_sync(0xffffffffu, p1, off);
            p2   += __shfl_xor_sync(0xffffffffu, p2, off);
        }

        float sc0 = p_in + p0;
        float sc1 = p_in + p1;
        float sc2 = p_in + p2;
        sc0 = sc0 >= 0.f ? sc0 : alpha * sc0;
        sc1 = sc1 >= 0.f ? sc1 : alpha * sc1;
        sc2 = sc2 >= 0.f ? sc2 : alpha * sc2;

        const float m = fmaxf(sc0, fmaxf(sc1, sc2));
        const float e0 = __expf(sc0 - m);
        const float e1 = __expf(sc1 - m);
        const float e2 = __expf(sc2 - m);
        const float inv = 1.0f / (e0 + e1 + e2);

        if (lane < SS) {
            const int b = idx >> 8;
            const int a = idx & 255;
            const float e = (lane == 0) ? e0 : (lane == 1 ? e1 : e2);
            out[((size_t)b * SS + lane) * AA + a] = e * inv;
        }

        // ---- Rotate pipeline ----
#pragma unroll
        for (int i = 0; i < 8; ++i) cur[i] = nxt[i];
        idx = nidx;
        valid = nvalid;
    }
}

extern "C" void kernel_launch(void* const* d_in, const int* in_sizes, int n_in,
                              void* d_out, int out_size)
{
    const float* input     = (const float*)d_in[0];  // (B, A, D) f32
    const float* scattered = (const float*)d_in[1];  // (B, S, A, D) f32
    const float* weight    = (const float*)d_in[2];  // (2D,) f32
    const float* prelu     = (const float*)d_in[3];  // (1,) f32
    float* out = (float*)d_out;                      // (B, S, A) f32

    spectral_attention_kernel<<<CTAS, 256>>>(input, scattered, weight, prelu, out);
}

// round 4
// speedup vs baseline: 1.0405x; 1.0405x over previous
#include <cuda_runtime.h>

// SpectralAttention: B=1024, S=3, A=256, D=256
// HBM-bound streaming reduction. R4 = R2 read path (front-batched 8x LDG.128,
// __ldcs, 4 CTAs/SM) + smem-staged coalesced output writes: per-block the 3x8
// results are staged in shared memory and written as 3 dense 32B sectors
// (instead of 24 sparse 4B stores dirtying 24 sectors -> ~22MB write traffic saved).

#define BB 1024
#define SS 3
#define AA 256
#define DD 256

__global__ __launch_bounds__(256, 4)
void spectral_attention_kernel(const float* __restrict__ input,
                               const float* __restrict__ scattered,
                               const float* __restrict__ weight,
                               const float* __restrict__ prelu,
                               float* __restrict__ out)
{
    __shared__ float sbuf[SS][8];   // [s][warp_in_block]

    const int lane = threadIdx.x & 31;
    const int wib  = threadIdx.x >> 5;                              // 0..7
    const int warp = (blockIdx.x * blockDim.x + threadIdx.x) >> 5;  // 0 .. B*A-1
    const int b = warp >> 8;    // / AA
    const int a = warp & 255;   // % AA

    // ---- Front-batch ALL stream loads (8x LDG.128, evict-first) ----
    const float4* __restrict__ xr =
        reinterpret_cast<const float4*>(input + (((size_t)b * AA + a) * DD));
    const float4* __restrict__ y0r = reinterpret_cast<const float4*>(
        scattered + ((((size_t)b * SS + 0) * AA + a) * (size_t)DD));
    const float4* __restrict__ y1r = reinterpret_cast<const float4*>(
        scattered + ((((size_t)b * SS + 1) * AA + a) * (size_t)DD));
    const float4* __restrict__ y2r = reinterpret_cast<const float4*>(
        scattered + ((((size_t)b * SS + 2) * AA + a) * (size_t)DD));

    const float4 x0  = __ldcs(&xr[lane]);
    const float4 x1  = __ldcs(&xr[lane + 32]);
    const float4 ya0 = __ldcs(&y0r[lane]);
    const float4 ya1 = __ldcs(&y0r[lane + 32]);
    const float4 yb0 = __ldcs(&y1r[lane]);
    const float4 yb1 = __ldcs(&y1r[lane + 32]);
    const float4 yc0 = __ldcs(&y2r[lane]);
    const float4 yc1 = __ldcs(&y2r[lane + 32]);

    // ---- Weights (512 floats = 128 float4): L1-resident after first wave ----
    const float4* __restrict__ wv = reinterpret_cast<const float4*>(weight);
    const float4 w1a = __ldg(&wv[lane]);
    const float4 w1b = __ldg(&wv[lane + 32]);
    const float4 w2a = __ldg(&wv[64 + lane]);
    const float4 w2b = __ldg(&wv[64 + lane + 32]);

    float p_in = x0.x * w1a.x + x0.y * w1a.y + x0.z * w1a.z + x0.w * w1a.w
               + x1.x * w1b.x + x1.y * w1b.y + x1.z * w1b.z + x1.w * w1b.w;
    float p0 = ya0.x * w2a.x + ya0.y * w2a.y + ya0.z * w2a.z + ya0.w * w2a.w
             + ya1.x * w2b.x + ya1.y * w2b.y + ya1.z * w2b.z + ya1.w * w2b.w;
    float p1 = yb0.x * w2a.x + yb0.y * w2a.y + yb0.z * w2a.z + yb0.w * w2a.w
             + yb1.x * w2b.x + yb1.y * w2b.y + yb1.z * w2b.z + yb1.w * w2b.w;
    float p2 = yc0.x * w2a.x + yc0.y * w2a.y + yc0.z * w2a.z + yc0.w * w2a.w
             + yc1.x * w2b.x + yc1.y * w2b.y + yc1.z * w2b.z + yc1.w * w2b.w;

    // Butterfly reduce all 4 partial dots.
#pragma unroll
    for (int off = 16; off > 0; off >>= 1) {
        p_in += __shfl_xor_sync(0xffffffffu, p_in, off);
        p0   += __shfl_xor_sync(0xffffffffu, p0, off);
        p1   += __shfl_xor_sync(0xffffffffu, p1, off);
        p2   += __shfl_xor_sync(0xffffffffu, p2, off);
    }

    const float alpha = __ldg(prelu);
    float sc0 = p_in + p0;
    float sc1 = p_in + p1;
    float sc2 = p_in + p2;
    sc0 = sc0 >= 0.f ? sc0 : alpha * sc0;
    sc1 = sc1 >= 0.f ? sc1 : alpha * sc1;
    sc2 = sc2 >= 0.f ? sc2 : alpha * sc2;

    const float m = fmaxf(sc0, fmaxf(sc1, sc2));
    const float e0 = __expf(sc0 - m);
    const float e1 = __expf(sc1 - m);
    const float e2 = __expf(sc2 - m);
    const float inv = 1.0f / (e0 + e1 + e2);

    if (lane < SS) {
        const float e = (lane == 0) ? e0 : (lane == 1 ? e1 : e2);
        sbuf[lane][wib] = e * inv;
    }

    __syncthreads();

    // ---- Coalesced output write: 24 threads -> 3 dense 32B sectors ----
    // Block covers a0..a0+7 of one b (256 a's / 8 warps = 32 blocks per b,
    // so a block never straddles b).
    const int tid = threadIdx.x;
    if (tid < SS * 8) {
        const int s = tid >> 3;        // 0..2
        const int i = tid & 7;         // 0..7
        const int bb = (blockIdx.x * 8) >> 8;
        const int a0 = (blockIdx.x * 8) & 255;
        __stcs(&out[((size_t)bb * SS + s) * AA + a0 + i], sbuf[s][i]);
    }
}

extern "C" void kernel_launch(void* const* d_in, const int* in_sizes, int n_in,
                              void* d_out, int out_size)
{
    const float* input     = (const float*)d_in[0];  // (B, A, D) f32
    const float* scattered = (const float*)d_in[1];  // (B, S, A, D) f32
    const float* weight    = (const float*)d_in[2];  // (2D,) f32
    const float* prelu     = (const float*)d_in[3];  // (1,) f32
    float* out = (float*)d_out;                      // (B, S, A) f32

    const int total_warps = BB * AA;                 // 262144
    const int threads = 256;                         // 8 warps / block
    const int blocks = total_warps / (threads / 32); // 32768
    spectral_attention_kernel<<<blocks, threads>>>(input, scattered, weight, prelu, out);
}